// round 6
// baseline (speedup 1.0000x reference)
#include <cuda_runtime.h>
#include <math.h>

#define N_NODES 50000
#define N_EDGES 1600000
#define N_HEADS 8
#define IN_DIM  512
#define OUT_DIM 64
#define FEAT_DIM 512   // N_HEADS * OUT_DIM
#define LRELU_ALPHA 0.2f
#define SCAN_NB 49     // ceil(50000 / 1024)

// ---------------- scratch (device globals; no allocation allowed) -----------
__device__ float g_feat[N_NODES * FEAT_DIM];     // 102.4 MB
__device__ float g_alpha_s[N_NODES * N_HEADS];
__device__ float g_alpha_d[N_NODES * N_HEADS];
__device__ int   g_deg[N_NODES];
__device__ int   g_cursor[N_NODES];
__device__ int   g_rowstart[N_NODES + 1];
__device__ int   g_csr_dst[N_EDGES];
__device__ int   g_bsum[64];
__device__ int   g_boff[64];

// ---------------- zero counters + alpha accumulators -------------------------
__global__ void zero_kernel() {
    int i = blockIdx.x * blockDim.x + threadIdx.x;
    int stride = gridDim.x * blockDim.x;
    for (int j = i; j < N_NODES * N_HEADS; j += stride) {
        g_alpha_s[j] = 0.f;
        g_alpha_d[j] = 0.f;
    }
    for (int j = i; j < N_NODES; j += stride) {
        g_deg[j] = 0;
        g_cursor[j] = 0;
    }
}

// ---------------- TF32 tensor-core GEMM: feat = x @ W (+ fused alpha) --------
// B[k][j] = W[h][k][o], h = j>>6, o = j&63  (j = GLOBAL column)
// BM=128, BN=128, BK=32; 8 warps x (64x32); 2-stage cp.async raw staging +
// per-tile smem convert(tf32)+permute into fragment-major A2/B2.
#define GEMM_BM 128
#define GEMM_BN 128
#define GEMM_BK 32
#define A_STRIDE 36     // raw staging strides (16B-aligned rows)
#define B_STRIDE 136
#define A_BUF_FLOATS (GEMM_BM * A_STRIDE)          // 4608
#define B_BUF_FLOATS (GEMM_BK * B_STRIDE)          // 4352
#define AB_TILE_FLOATS 4096                        // 128*32 = 32*128
// smem: raw[2][A+B] + A2[4096] + B2[4096]
#define GEMM_SMEM_BYTES ((2 * (A_BUF_FLOATS + B_BUF_FLOATS) + 2 * AB_TILE_FLOATS) * 4)

__device__ __forceinline__ unsigned f2tf(float f) {
    unsigned r;
    asm("cvt.rna.tf32.f32 %0, %1;" : "=r"(r) : "f"(f));
    return r;
}

__device__ __forceinline__ void mma_tf32(float* c, const unsigned* a, const unsigned* b) {
    asm volatile(
        "mma.sync.aligned.m16n8k8.row.col.f32.tf32.tf32.f32 "
        "{%0,%1,%2,%3},{%4,%5,%6,%7},{%8,%9},{%0,%1,%2,%3};"
        : "+f"(c[0]), "+f"(c[1]), "+f"(c[2]), "+f"(c[3])
        : "r"(a[0]), "r"(a[1]), "r"(a[2]), "r"(a[3]), "r"(b[0]), "r"(b[1]));
}

__device__ __forceinline__ void cp_async16(unsigned saddr, const void* g, int srcbytes) {
    asm volatile("cp.async.cg.shared.global [%0], [%1], 16, %2;\n"
                 :: "r"(saddr), "l"(g), "r"(srcbytes));
}
__device__ __forceinline__ void cp_commit() {
    asm volatile("cp.async.commit_group;\n");
}
__device__ __forceinline__ void cp_wait0() {
    asm volatile("cp.async.wait_group 0;\n");
}

__global__ __launch_bounds__(256, 2) void gemm_tf32_kernel(const float* __restrict__ x,
                                                           const float* __restrict__ W,
                                                           const float* __restrict__ att_w) {
    extern __shared__ float smem[];
    float* Asm = smem;                                  // [2][128][A_STRIDE] raw
    float* Bsm = smem + 2 * A_BUF_FLOATS;               // [2][32][B_STRIDE] raw
    float* A2  = smem + 2 * (A_BUF_FLOATS + B_BUF_FLOATS);          // [4][8][32][4]
    float* B2  = A2 + AB_TILE_FLOATS;                               // [4][16][32][2]
    unsigned sbaseA = (unsigned)__cvta_generic_to_shared(Asm);
    unsigned sbaseB = (unsigned)__cvta_generic_to_shared(Bsm);
#define AS(b, r, k) Asm[(b) * A_BUF_FLOATS + (r) * A_STRIDE + (k)]
#define BS(b, k, n) Bsm[(b) * B_BUF_FLOATS + (k) * B_STRIDE + (n)]

    const int t    = threadIdx.x;
    const int lane = t & 31;
    const int wid  = t >> 5;
    const int row0 = blockIdx.y * GEMM_BM;
    const int col0 = blockIdx.x * GEMM_BN;

    const int wm = (wid & 1) * 64;       // warp M offset
    const int wn = (wid >> 1) * 32;      // warp N offset
    const int wmb = (wid & 1) * 4;       // warp m16-block offset (wm/16)
    const int wnb = (wid >> 1) * 4;      // warp n8-block offset (wn/8)
    const int fr = lane >> 2;            // 0..7
    const int fc = lane & 3;             // 0..3

    // ---- cp.async index precompute (4 x 16B per thread per tile, A and B) ----
    int arow[4], ak[4], avalid[4];
    int bk[4], bcol[4];
    const float* aptr[4];
    const float* bptr[4];
#pragma unroll
    for (int i = 0; i < 4; i++) {
        int pos = t + 256 * i;
        arow[i] = pos >> 3;
        ak[i]   = (pos & 7) * 4;
        int gr  = row0 + arow[i];
        avalid[i] = (gr < N_NODES) ? 16 : 0;
        aptr[i] = x + (long)gr * IN_DIM + ak[i];
        bk[i]   = pos >> 5;
        bcol[i] = (pos & 31) * 4;
        int gj  = col0 + bcol[i];
        bptr[i] = W + ((long)(gj >> 6) * IN_DIM + bk[i]) * OUT_DIM + (gj & 63);
    }

    float acc[4][4][4];
#pragma unroll
    for (int mt = 0; mt < 4; mt++)
#pragma unroll
        for (int nt = 0; nt < 4; nt++)
#pragma unroll
            for (int i = 0; i < 4; i++) acc[mt][nt][i] = 0.f;

    const int NKT = IN_DIM / GEMM_BK;   // 16

    auto issue_tile = [&](int s, int buf) {
        int koff = s * GEMM_BK;
#pragma unroll
        for (int i = 0; i < 4; i++) {
            unsigned da = sbaseA + (buf * A_BUF_FLOATS + arow[i] * A_STRIDE + ak[i]) * 4u;
            cp_async16(da, aptr[i] + koff, avalid[i]);
            unsigned db = sbaseB + (buf * B_BUF_FLOATS + bk[i] * B_STRIDE + bcol[i]) * 4u;
            cp_async16(db, bptr[i] + (long)koff * OUT_DIM, 16);
        }
        cp_commit();
    };

    issue_tile(0, 0);

    for (int kt = 0; kt < NKT; kt++) {
        cp_wait0();               // raw tile kt resident (only group outstanding)
        __syncthreads();          // raw buf free check + prev mma done with A2/B2

        if (kt + 1 < NKT) issue_tile(kt + 1, (kt + 1) & 1);
        int cur = kt & 1;

        // ---- convert + permute pass: raw f32 -> tf32 fragment-major ----
        // A2[ks][mblk][lane][j] = tf32(A[mblk*16 + fr + (j&1)*8][ks*8 + fc + (j>>1)*4])
#pragma unroll
        for (int p = 0; p < 4; p++) {
            int q = t + 256 * p;            // float4 output index
            int l_  = q & 31, mb = (q >> 5) & 7, ks = q >> 8;
            int fr_ = l_ >> 2, fc_ = l_ & 3;
            int r_ = mb * 16 + fr_, c_ = ks * 8 + fc_;
            float4 v;
            v.x = AS(cur, r_,     c_);
            v.y = AS(cur, r_ + 8, c_);
            v.z = AS(cur, r_,     c_ + 4);
            v.w = AS(cur, r_ + 8, c_ + 4);
            v.x = __uint_as_float(f2tf(v.x));
            v.y = __uint_as_float(f2tf(v.y));
            v.z = __uint_as_float(f2tf(v.z));
            v.w = __uint_as_float(f2tf(v.w));
            *(float4*)&A2[q * 4] = v;
        }
        // B2[ks][nblk][lane][j] = tf32(B[ks*8 + fc + j*4][nblk*8 + fr])
#pragma unroll
        for (int p = 0; p < 8; p++) {
            int q = t + 256 * p;            // float2 output index
            int l_  = q & 31, nb = (q >> 5) & 15, ks = q >> 9;
            int fr_ = l_ >> 2, fc_ = l_ & 3;
            int r_ = ks * 8 + fc_, c_ = nb * 8 + fr_;
            float2 v;
            v.x = BS(cur, r_,     c_);
            v.y = BS(cur, r_ + 4, c_);
            v.x = __uint_as_float(f2tf(v.x));
            v.y = __uint_as_float(f2tf(v.y));
            *(float2*)&B2[q * 2] = v;
        }
        __syncthreads();

        // ---- mma mainloop: vector fragment loads, zero cvt ----
#pragma unroll
        for (int ks = 0; ks < 4; ks++) {
            unsigned af[4][4], bf[4][2];
#pragma unroll
            for (int mt = 0; mt < 4; mt++)
                *(uint4*)af[mt] = *(const uint4*)&A2[(((ks * 8) + wmb + mt) * 32 + lane) * 4];
#pragma unroll
            for (int nt = 0; nt < 4; nt++)
                *(uint2*)bf[nt] = *(const uint2*)&B2[(((ks * 16) + wnb + nt) * 32 + lane) * 2];
#pragma unroll
            for (int mt = 0; mt < 4; mt++)
#pragma unroll
                for (int nt = 0; nt < 4; nt++)
                    mma_tf32(acc[mt][nt], af[mt], bf[nt]);
        }
    }

    // ---- epilogue: store feat ----
#pragma unroll
    for (int mt = 0; mt < 4; mt++) {
#pragma unroll
        for (int nt = 0; nt < 4; nt++) {
            int row = row0 + wm + mt * 16 + fr;
            int col = col0 + wn + nt * 8 + 2 * fc;
            if (row < N_NODES)
                *(float2*)&g_feat[(long)row * FEAT_DIM + col] =
                    make_float2(acc[mt][nt][0], acc[mt][nt][1]);
            if (row + 8 < N_NODES)
                *(float2*)&g_feat[(long)(row + 8) * FEAT_DIM + col] =
                    make_float2(acc[mt][nt][2], acc[mt][nt][3]);
        }
    }

    // ---- epilogue: fused alpha partial dots (warp cols all in one head) ----
    {
        int head = (col0 + wn) >> 6;
        const float* a1 = att_w + head * (2 * OUT_DIM);
        const float* a2 = a1 + OUT_DIM;
        float s1[8], s2[8];
#pragma unroll
        for (int i = 0; i < 8; i++) { s1[i] = 0.f; s2[i] = 0.f; }
#pragma unroll
        for (int nt = 0; nt < 4; nt++) {
            int o = (wn & 63) + nt * 8 + 2 * fc;
            float w10 = a1[o], w11 = a1[o + 1];
            float w20 = a2[o], w21 = a2[o + 1];
#pragma unroll
            for (int mt = 0; mt < 4; mt++) {
                s1[mt*2]   = fmaf(acc[mt][nt][0], w10, fmaf(acc[mt][nt][1], w11, s1[mt*2]));
                s1[mt*2+1] = fmaf(acc[mt][nt][2], w10, fmaf(acc[mt][nt][3], w11, s1[mt*2+1]));
                s2[mt*2]   = fmaf(acc[mt][nt][0], w20, fmaf(acc[mt][nt][1], w21, s2[mt*2]));
                s2[mt*2+1] = fmaf(acc[mt][nt][2], w20, fmaf(acc[mt][nt][3], w21, s2[mt*2+1]));
            }
        }
#pragma unroll
        for (int i = 0; i < 8; i++) {
            s1[i] += __shfl_xor_sync(0xffffffffu, s1[i], 1);
            s1[i] += __shfl_xor_sync(0xffffffffu, s1[i], 2);
            s2[i] += __shfl_xor_sync(0xffffffffu, s2[i], 1);
            s2[i] += __shfl_xor_sync(0xffffffffu, s2[i], 2);
        }
        if (fc == 0) {
#pragma unroll
            for (int i = 0; i < 8; i++) {
                int row = row0 + wm + (i >> 1) * 16 + fr + (i & 1) * 8;
                if (row < N_NODES) {
                    atomicAdd(&g_alpha_s[row * N_HEADS + head], s1[i]);
                    atomicAdd(&g_alpha_d[row * N_HEADS + head], s2[i]);
                }
            }
        }
    }
#undef AS
#undef BS
}

// ---------------- CSR construction -------------------------------------------
__global__ void count_kernel(const int* __restrict__ src) {
    int e = blockIdx.x * blockDim.x + threadIdx.x;
    if (e < N_EDGES) atomicAdd(&g_deg[src[e]], 1);
}

// 3-phase scan: block-local scan -> scan of block sums -> add offsets
__global__ __launch_bounds__(1024) void scan1_kernel() {
    __shared__ int wsum[32];
    int tid = threadIdx.x, b = blockIdx.x;
    int i = b * 1024 + tid;
    int lane = tid & 31, wp = tid >> 5;
    int v = (i < N_NODES) ? g_deg[i] : 0;
    int x = v;
#pragma unroll
    for (int off = 1; off < 32; off <<= 1) {
        int y = __shfl_up_sync(0xffffffffu, x, off);
        if (lane >= off) x += y;
    }
    if (lane == 31) wsum[wp] = x;
    __syncthreads();
    if (wp == 0) {
        int s = wsum[lane];
#pragma unroll
        for (int off = 1; off < 32; off <<= 1) {
            int y = __shfl_up_sync(0xffffffffu, s, off);
            if (lane >= off) s += y;
        }
        wsum[lane] = s;
    }
    __syncthreads();
    int incl = x + (wp ? wsum[wp - 1] : 0);
    if (i < N_NODES) g_rowstart[i] = incl - v;   // block-local exclusive
    if (tid == 1023) g_bsum[b] = incl;
}

__global__ void scan2_kernel() {   // 1 block, 64 threads, SCAN_NB=49 sums
    __shared__ int t0;
    int tid = threadIdx.x, lane = tid & 31, wp = tid >> 5;
    int v = (tid < SCAN_NB) ? g_bsum[tid] : 0;
    int x = v;
#pragma unroll
    for (int off = 1; off < 32; off <<= 1) {
        int y = __shfl_up_sync(0xffffffffu, x, off);
        if (lane >= off) x += y;
    }
    if (wp == 0 && lane == 31) t0 = x;
    __syncthreads();
    int incl = x + (wp ? t0 : 0);
    if (tid < SCAN_NB) g_boff[tid] = incl - v;
    if (tid == SCAN_NB - 1) g_rowstart[N_NODES] = incl;
}

__global__ __launch_bounds__(1024) void scan3_kernel() {
    int i = blockIdx.x * 1024 + threadIdx.x;
    if (i < N_NODES) g_rowstart[i] += g_boff[blockIdx.x];
}

__global__ void fill_kernel(const int* __restrict__ src, const int* __restrict__ dst) {
    int e = blockIdx.x * blockDim.x + threadIdx.x;
    if (e < N_EDGES) {
        int s = src[e];
        int p = atomicAdd(&g_cursor[s], 1);
        g_csr_dst[g_rowstart[s] + p] = dst[e];
    }
}

// ---------------- per-node softmax + aggregation (no max pass) ---------------
// one block (256 threads = 8 warps) per src node
__global__ __launch_bounds__(256) void agg_kernel(float* __restrict__ out) {
    int n   = blockIdx.x;
    int tid = threadIdx.x;
    int rs  = g_rowstart[n];
    int deg = g_rowstart[n + 1] - rs;

    __shared__ float s_as[N_HEADS];
    __shared__ float s_inv[N_HEADS];
    __shared__ int   s_d[32];
    __shared__ float s_att[32 * N_HEADS];

    // ---- phase A: per-head exp-sum (warp w = head w); logits are O(±6), safe
    int w = tid >> 5, l = tid & 31;
    float as = g_alpha_s[n * N_HEADS + w];
    float s = 0.f;
    for (int e = l; e < deg; e += 32) {
        int d = g_csr_dst[rs + e];
        float v = as + g_alpha_d[d * N_HEADS + w];
        v = (v > 0.f) ? v : LRELU_ALPHA * v;
        s += __expf(v);
    }
#pragma unroll
    for (int o = 16; o; o >>= 1) s += __shfl_xor_sync(0xffffffffu, s, o);
    if (l == 0) {
        s_as[w]  = as;
        s_inv[w] = (deg > 0) ? (1.0f / s) : 0.f;
    }
    __syncthreads();

    // ---- phase B: weighted gather-accumulate ----
    float2 acc = make_float2(0.f, 0.f);
    const float2* f2 = (const float2*)g_feat;
    int hh = tid >> 5;                    // head for columns [tid*2, tid*2+1]

    for (int c = 0; c < deg; c += 32) {
        int len = min(32, deg - c);
        __syncthreads();                  // protect s_d/s_att reuse
        if (tid < len) s_d[tid] = g_csr_dst[rs + c + tid];
        __syncthreads();
        {
            int i = tid >> 3, h = tid & 7;
            if (i < len) {
                int d = s_d[i];
                float v = s_as[h] + g_alpha_d[d * N_HEADS + h];
                v = (v > 0.f) ? v : LRELU_ALPHA * v;
                s_att[i * 8 + h] = __expf(v) * s_inv[h];
            }
        }
        __syncthreads();
        for (int i = 0; i < len; i++) {
            int d = s_d[i];
            float a = s_att[i * 8 + hh];
            float2 f = f2[(long)d * (FEAT_DIM / 2) + tid];
            acc.x = fmaf(a, f.x, acc.x);
            acc.y = fmaf(a, f.y, acc.y);
        }
    }

    float2* o2 = (float2*)out;
    o2[(long)n * (FEAT_DIM / 2) + tid] =
        make_float2(fmaxf(acc.x, 0.f), fmaxf(acc.y, 0.f));
}

// ---------------- launch ------------------------------------------------------
extern "C" void kernel_launch(void* const* d_in, const int* in_sizes, int n_in,
                              void* d_out, int out_size) {
    const float* x     = (const float*)d_in[0];
    const float* W     = (const float*)d_in[1];
    const float* att_w = (const float*)d_in[2];
    const int*   src   = (const int*)d_in[3];
    const int*   dst   = (const int*)d_in[4];
    float* out = (float*)d_out;

    cudaFuncSetAttribute(gemm_tf32_kernel,
                         cudaFuncAttributeMaxDynamicSharedMemorySize, GEMM_SMEM_BYTES);

    // gemm placed 4th: ncu empirically captures the 4th launch
    zero_kernel<<<512, 256>>>();
    count_kernel<<<(N_EDGES + 255) / 256, 256>>>(src);
    scan1_kernel<<<SCAN_NB, 1024>>>();
    gemm_tf32_kernel<<<dim3(FEAT_DIM / GEMM_BN, (N_NODES + GEMM_BM - 1) / GEMM_BM),
                       256, GEMM_SMEM_BYTES>>>(x, W, att_w);
    scan2_kernel<<<1, 64>>>();
    scan3_kernel<<<SCAN_NB, 1024>>>();
    fill_kernel<<<(N_EDGES + 255) / 256, 256>>>(src, dst);
    agg_kernel<<<N_NODES, 256>>>(out);
}

// round 8
// speedup vs baseline: 1.1839x; 1.1839x over previous
#include <cuda_runtime.h>
#include <cuda_fp16.h>
#include <math.h>

#define N_NODES 50000
#define N_EDGES 1600000
#define N_HEADS 8
#define IN_DIM  512
#define OUT_DIM 64
#define FEAT_DIM 512   // N_HEADS * OUT_DIM
#define LRELU_ALPHA 0.2f
#define SCAN_NB 49     // ceil(50000 / 1024)

// ---------------- scratch (device globals; no allocation allowed) -----------
__device__ __half g_feath[N_NODES * FEAT_DIM];   // 51.2 MB (gather source, fp16)
__device__ float g_alpha_s[N_NODES * N_HEADS];
__device__ float g_alpha_d[N_NODES * N_HEADS];
__device__ int   g_deg[N_NODES];
__device__ int   g_cursor[N_NODES];
__device__ int   g_rowstart[N_NODES + 1];
__device__ int   g_csr_dst[N_EDGES];
__device__ int   g_bsum[64];
__device__ int   g_boff[64];

// ---------------- zero counters + alpha accumulators -------------------------
__global__ void zero_kernel() {
    int i = blockIdx.x * blockDim.x + threadIdx.x;
    int stride = gridDim.x * blockDim.x;
    for (int j = i; j < N_NODES * N_HEADS; j += stride) {
        g_alpha_s[j] = 0.f;
        g_alpha_d[j] = 0.f;
    }
    for (int j = i; j < N_NODES; j += stride) {
        g_deg[j] = 0;
        g_cursor[j] = 0;
    }
}

// ---------------- TF32 tensor-core GEMM: feat = x @ W (+ fused alpha) --------
// (Round-5 structure: 3-stage cp.async, cvt at fragment load)
// B[k][j] = W[h][k][o], h = j>>6, o = j&63  (j = GLOBAL column)
#define GEMM_BM 128
#define GEMM_BN 128
#define GEMM_BK 32
#define GEMM_STAGES 3
#define A_STRIDE 36     // floats; 144 B (16B-aligned); (4*fr+fc)%32 distinct
#define B_STRIDE 136    // floats; 544 B (16B-aligned); (8*fc+fr)%32 distinct
#define A_BUF_FLOATS (GEMM_BM * A_STRIDE)          // 4608
#define B_BUF_FLOATS (GEMM_BK * B_STRIDE)          // 4352
#define GEMM_SMEM_BYTES (GEMM_STAGES * (A_BUF_FLOATS + B_BUF_FLOATS) * 4)  // 107520

__device__ __forceinline__ unsigned f2tf(float f) {
    unsigned r;
    asm("cvt.rna.tf32.f32 %0, %1;" : "=r"(r) : "f"(f));
    return r;
}

__device__ __forceinline__ void mma_tf32(float* c, const unsigned* a, const unsigned* b) {
    asm volatile(
        "mma.sync.aligned.m16n8k8.row.col.f32.tf32.tf32.f32 "
        "{%0,%1,%2,%3},{%4,%5,%6,%7},{%8,%9},{%0,%1,%2,%3};"
        : "+f"(c[0]), "+f"(c[1]), "+f"(c[2]), "+f"(c[3])
        : "r"(a[0]), "r"(a[1]), "r"(a[2]), "r"(a[3]), "r"(b[0]), "r"(b[1]));
}

__device__ __forceinline__ void cp_async16(unsigned saddr, const void* g, int srcbytes) {
    asm volatile("cp.async.cg.shared.global [%0], [%1], 16, %2;\n"
                 :: "r"(saddr), "l"(g), "r"(srcbytes));
}
__device__ __forceinline__ void cp_commit() {
    asm volatile("cp.async.commit_group;\n");
}
__device__ __forceinline__ void cp_wait1() {
    asm volatile("cp.async.wait_group 1;\n");
}

__global__ __launch_bounds__(256) void gemm_tf32_kernel(const float* __restrict__ x,
                                                        const float* __restrict__ W,
                                                        const float* __restrict__ att_w) {
    extern __shared__ float smem[];
    float* Asm = smem;                                        // [S][128][A_STRIDE]
    float* Bsm = smem + GEMM_STAGES * A_BUF_FLOATS;           // [S][32][B_STRIDE]
    unsigned sbaseA = (unsigned)__cvta_generic_to_shared(Asm);
    unsigned sbaseB = (unsigned)__cvta_generic_to_shared(Bsm);
#define AS(b, r, k) Asm[(b) * A_BUF_FLOATS + (r) * A_STRIDE + (k)]
#define BS(b, k, n) Bsm[(b) * B_BUF_FLOATS + (k) * B_STRIDE + (n)]

    const int t    = threadIdx.x;
    const int lane = t & 31;
    const int wid  = t >> 5;
    const int row0 = blockIdx.y * GEMM_BM;
    const int col0 = blockIdx.x * GEMM_BN;

    const int wm = (wid & 1) * 64;
    const int wn = (wid >> 1) * 32;
    const int fr = lane >> 2;   // 0..7
    const int fc = lane & 3;    // 0..3

    // ---- cp.async index precompute (4 x 16B per thread per tile, A and B) ----
    int arow[4], ak[4], avalid[4];
    int bk[4], bcol[4];
    const float* aptr[4];
    const float* bptr[4];
#pragma unroll
    for (int i = 0; i < 4; i++) {
        int pos = t + 256 * i;
        arow[i] = pos >> 3;
        ak[i]   = (pos & 7) * 4;
        int gr  = row0 + arow[i];
        avalid[i] = (gr < N_NODES) ? 16 : 0;
        aptr[i] = x + (long)gr * IN_DIM + ak[i];
        bk[i]   = pos >> 5;
        bcol[i] = (pos & 31) * 4;
        int gj  = col0 + bcol[i];
        bptr[i] = W + ((long)(gj >> 6) * IN_DIM + bk[i]) * OUT_DIM + (gj & 63);
    }

    float acc[4][4][4];
#pragma unroll
    for (int mt = 0; mt < 4; mt++)
#pragma unroll
        for (int nt = 0; nt < 4; nt++)
#pragma unroll
            for (int i = 0; i < 4; i++) acc[mt][nt][i] = 0.f;

    const int NKT = IN_DIM / GEMM_BK;   // 16

    auto issue_tile = [&](int s, int buf) {
        int koff = s * GEMM_BK;
#pragma unroll
        for (int i = 0; i < 4; i++) {
            unsigned da = sbaseA + (buf * A_BUF_FLOATS + arow[i] * A_STRIDE + ak[i]) * 4u;
            cp_async16(da, aptr[i] + koff, avalid[i]);
            unsigned db = sbaseB + (buf * B_BUF_FLOATS + bk[i] * B_STRIDE + bcol[i]) * 4u;
            cp_async16(db, bptr[i] + (long)koff * OUT_DIM, 16);
        }
        cp_commit();
    };

    // ---- prologue: prefetch tiles 0,1 ----
    issue_tile(0, 0);
    issue_tile(1, 1);

    for (int kt = 0; kt < NKT; kt++) {
        cp_wait1();               // tile kt resident
        __syncthreads();          // all threads done with buf[(kt+2)%3] compute

        if (kt + 2 < NKT) issue_tile(kt + 2, (kt + 2) % GEMM_STAGES);
        else              cp_commit();   // dummy group keeps wait_group<1> uniform

        int cur = kt % GEMM_STAGES;
#pragma unroll
        for (int ks = 0; ks < 4; ks++) {
            int k0 = ks * 8;
            unsigned af[4][4], bf[4][2];
#pragma unroll
            for (int mt = 0; mt < 4; mt++) {
                int r0 = wm + mt * 16 + fr;
                af[mt][0] = f2tf(AS(cur, r0,     k0 + fc));
                af[mt][1] = f2tf(AS(cur, r0 + 8, k0 + fc));
                af[mt][2] = f2tf(AS(cur, r0,     k0 + fc + 4));
                af[mt][3] = f2tf(AS(cur, r0 + 8, k0 + fc + 4));
            }
#pragma unroll
            for (int nt = 0; nt < 4; nt++) {
                int n0 = wn + nt * 8 + fr;
                bf[nt][0] = f2tf(BS(cur, k0 + fc,     n0));
                bf[nt][1] = f2tf(BS(cur, k0 + fc + 4, n0));
            }
#pragma unroll
            for (int mt = 0; mt < 4; mt++)
#pragma unroll
                for (int nt = 0; nt < 4; nt++)
                    mma_tf32(acc[mt][nt], af[mt], bf[nt]);
        }
    }

    // ---- epilogue: store feat as fp16 (gather source; halves agg traffic) ----
#pragma unroll
    for (int mt = 0; mt < 4; mt++) {
#pragma unroll
        for (int nt = 0; nt < 4; nt++) {
            int row = row0 + wm + mt * 16 + fr;
            int col = col0 + wn + nt * 8 + 2 * fc;
            if (row < N_NODES)
                *(__half2*)&g_feath[(long)row * FEAT_DIM + col] =
                    __floats2half2_rn(acc[mt][nt][0], acc[mt][nt][1]);
            if (row + 8 < N_NODES)
                *(__half2*)&g_feath[(long)(row + 8) * FEAT_DIM + col] =
                    __floats2half2_rn(acc[mt][nt][2], acc[mt][nt][3]);
        }
    }

    // ---- epilogue: fused alpha partial dots (f32 accs; warp cols in one head) --
    {
        int head = (col0 + wn) >> 6;
        const float* a1 = att_w + head * (2 * OUT_DIM);
        const float* a2 = a1 + OUT_DIM;
        float s1[8], s2[8];
#pragma unroll
        for (int i = 0; i < 8; i++) { s1[i] = 0.f; s2[i] = 0.f; }
#pragma unroll
        for (int nt = 0; nt < 4; nt++) {
            int o = (wn & 63) + nt * 8 + 2 * fc;
            float w10 = a1[o], w11 = a1[o + 1];
            float w20 = a2[o], w21 = a2[o + 1];
#pragma unroll
            for (int mt = 0; mt < 4; mt++) {
                s1[mt*2]   = fmaf(acc[mt][nt][0], w10, fmaf(acc[mt][nt][1], w11, s1[mt*2]));
                s1[mt*2+1] = fmaf(acc[mt][nt][2], w10, fmaf(acc[mt][nt][3], w11, s1[mt*2+1]));
                s2[mt*2]   = fmaf(acc[mt][nt][0], w20, fmaf(acc[mt][nt][1], w21, s2[mt*2]));
                s2[mt*2+1] = fmaf(acc[mt][nt][2], w20, fmaf(acc[mt][nt][3], w21, s2[mt*2+1]));
            }
        }
#pragma unroll
        for (int i = 0; i < 8; i++) {
            s1[i] += __shfl_xor_sync(0xffffffffu, s1[i], 1);
            s1[i] += __shfl_xor_sync(0xffffffffu, s1[i], 2);
            s2[i] += __shfl_xor_sync(0xffffffffu, s2[i], 1);
            s2[i] += __shfl_xor_sync(0xffffffffu, s2[i], 2);
        }
        if (fc == 0) {
#pragma unroll
            for (int i = 0; i < 8; i++) {
                int row = row0 + wm + (i >> 1) * 16 + fr + (i & 1) * 8;
                if (row < N_NODES) {
                    atomicAdd(&g_alpha_s[row * N_HEADS + head], s1[i]);
                    atomicAdd(&g_alpha_d[row * N_HEADS + head], s2[i]);
                }
            }
        }
    }
#undef AS
#undef BS
}

// ---------------- CSR construction -------------------------------------------
__global__ void count_kernel(const int* __restrict__ src) {
    int e = blockIdx.x * blockDim.x + threadIdx.x;
    if (e < N_EDGES) atomicAdd(&g_deg[src[e]], 1);
}

// 3-phase scan: block-local scan -> scan of block sums -> add offsets
__global__ __launch_bounds__(1024) void scan1_kernel() {
    __shared__ int wsum[32];
    int tid = threadIdx.x, b = blockIdx.x;
    int i = b * 1024 + tid;
    int lane = tid & 31, wp = tid >> 5;
    int v = (i < N_NODES) ? g_deg[i] : 0;
    int x = v;
#pragma unroll
    for (int off = 1; off < 32; off <<= 1) {
        int y = __shfl_up_sync(0xffffffffu, x, off);
        if (lane >= off) x += y;
    }
    if (lane == 31) wsum[wp] = x;
    __syncthreads();
    if (wp == 0) {
        int s = wsum[lane];
#pragma unroll
        for (int off = 1; off < 32; off <<= 1) {
            int y = __shfl_up_sync(0xffffffffu, s, off);
            if (lane >= off) s += y;
        }
        wsum[lane] = s;
    }
    __syncthreads();
    int incl = x + (wp ? wsum[wp - 1] : 0);
    if (i < N_NODES) g_rowstart[i] = incl - v;   // block-local exclusive
    if (tid == 1023) g_bsum[b] = incl;
}

__global__ void scan2_kernel() {   // 1 block, 64 threads, SCAN_NB=49 sums
    __shared__ int t0;
    int tid = threadIdx.x, lane = tid & 31, wp = tid >> 5;
    int v = (tid < SCAN_NB) ? g_bsum[tid] : 0;
    int x = v;
#pragma unroll
    for (int off = 1; off < 32; off <<= 1) {
        int y = __shfl_up_sync(0xffffffffu, x, off);
        if (lane >= off) x += y;
    }
    if (wp == 0 && lane == 31) t0 = x;
    __syncthreads();
    int incl = x + (wp ? t0 : 0);
    if (tid < SCAN_NB) g_boff[tid] = incl - v;
    if (tid == SCAN_NB - 1) g_rowstart[N_NODES] = incl;
}

__global__ __launch_bounds__(1024) void scan3_kernel() {
    int i = blockIdx.x * 1024 + threadIdx.x;
    if (i < N_NODES) g_rowstart[i] += g_boff[blockIdx.x];
}

__global__ void fill_kernel(const int* __restrict__ src, const int* __restrict__ dst) {
    int e = blockIdx.x * blockDim.x + threadIdx.x;
    if (e < N_EDGES) {
        int s = src[e];
        int p = atomicAdd(&g_cursor[s], 1);
        g_csr_dst[g_rowstart[s] + p] = dst[e];
    }
}

// ---------------- per-node softmax + aggregation (fp16 gather) ---------------
// one block (256 threads = 8 warps) per src node
__global__ __launch_bounds__(256) void agg_kernel(float* __restrict__ out) {
    int n   = blockIdx.x;
    int tid = threadIdx.x;
    int rs  = g_rowstart[n];
    int deg = g_rowstart[n + 1] - rs;

    __shared__ float s_as[N_HEADS];
    __shared__ float s_inv[N_HEADS];
    __shared__ int   s_d[32];
    __shared__ float s_att[32 * N_HEADS];

    // ---- phase A: per-head exp-sum (warp w = head w); logits are O(±6), safe
    int w = tid >> 5, l = tid & 31;
    float as = g_alpha_s[n * N_HEADS + w];
    float s = 0.f;
    for (int e = l; e < deg; e += 32) {
        int d = g_csr_dst[rs + e];
        float v = as + g_alpha_d[d * N_HEADS + w];
        v = (v > 0.f) ? v : LRELU_ALPHA * v;
        s += __expf(v);
    }
#pragma unroll
    for (int o = 16; o; o >>= 1) s += __shfl_xor_sync(0xffffffffu, s, o);
    if (l == 0) {
        s_as[w]  = as;
        s_inv[w] = (deg > 0) ? (1.0f / s) : 0.f;
    }
    __syncthreads();

    // ---- phase B: weighted gather-accumulate (half2, 4B/thread/edge) ----
    float2 acc = make_float2(0.f, 0.f);
    const __half2* fh = (const __half2*)g_feath;
    int hh = tid >> 5;                    // head for columns [tid*2, tid*2+1]

    for (int c = 0; c < deg; c += 32) {
        int len = min(32, deg - c);
        __syncthreads();                  // protect s_d/s_att reuse
        if (tid < len) s_d[tid] = g_csr_dst[rs + c + tid];
        __syncthreads();
        {
            int i = tid >> 3, h = tid & 7;
            if (i < len) {
                int d = s_d[i];
                float v = s_as[h] + g_alpha_d[d * N_HEADS + h];
                v = (v > 0.f) ? v : LRELU_ALPHA * v;
                s_att[i * 8 + h] = __expf(v) * s_inv[h];
            }
        }
        __syncthreads();
        for (int i = 0; i < len; i++) {
            int d = s_d[i];
            float a = s_att[i * 8 + hh];
            float2 f = __half22float2(fh[(long)d * (FEAT_DIM / 2) + tid]);
            acc.x = fmaf(a, f.x, acc.x);
            acc.y = fmaf(a, f.y, acc.y);
        }
    }

    float2* o2 = (float2*)out;
    o2[(long)n * (FEAT_DIM / 2) + tid] =
        make_float2(fmaxf(acc.x, 0.f), fmaxf(acc.y, 0.f));
}

// ---------------- launch ------------------------------------------------------
extern "C" void kernel_launch(void* const* d_in, const int* in_sizes, int n_in,
                              void* d_out, int out_size) {
    const float* x     = (const float*)d_in[0];
    const float* W     = (const float*)d_in[1];
    const float* att_w = (const float*)d_in[2];
    const int*   src   = (const int*)d_in[3];
    const int*   dst   = (const int*)d_in[4];
    float* out = (float*)d_out;

    cudaFuncSetAttribute(gemm_tf32_kernel,
                         cudaFuncAttributeMaxDynamicSharedMemorySize, GEMM_SMEM_BYTES);

    // gemm placed 4th: ncu empirically captures the 4th launch
    zero_kernel<<<512, 256>>>();
    count_kernel<<<(N_EDGES + 255) / 256, 256>>>(src);
    scan1_kernel<<<SCAN_NB, 1024>>>();
    gemm_tf32_kernel<<<dim3(FEAT_DIM / GEMM_BN, (N_NODES + GEMM_BM - 1) / GEMM_BM),
                       256, GEMM_SMEM_BYTES>>>(x, W, att_w);
    scan2_kernel<<<1, 64>>>();
    scan3_kernel<<<SCAN_NB, 1024>>>();
    fill_kernel<<<(N_EDGES + 255) / 256, 256>>>(src, dst);
    agg_kernel<<<N_NODES, 256>>>(out);
}

// round 9
// speedup vs baseline: 1.2956x; 1.0943x over previous
#include <cuda_runtime.h>
#include <cuda_fp16.h>
#include <math.h>

#define N_NODES 50000
#define N_EDGES 1600000
#define N_HEADS 8
#define IN_DIM  512
#define OUT_DIM 64
#define FEAT_DIM 512   // N_HEADS * OUT_DIM
#define LRELU_ALPHA 0.2f
#define SCAN_NB 49     // ceil(50000 / 1024)

// ---------------- scratch (device globals; no allocation allowed) -----------
__device__ __half g_xh[N_NODES * IN_DIM];        // 51.2 MB fp16 copy of x
__device__ __half g_wh[FEAT_DIM * IN_DIM];       // 0.5 MB  B^T[j][k] fp16
__device__ __half g_feath[N_NODES * FEAT_DIM];   // 51.2 MB (gather source, fp16)
__device__ float g_alpha_s[N_NODES * N_HEADS];
__device__ float g_alpha_d[N_NODES * N_HEADS];
__device__ int   g_deg[N_NODES];
__device__ int   g_cursor[N_NODES];
__device__ int   g_rowstart[N_NODES + 1];
__device__ int   g_csr_dst[N_EDGES];
__device__ int   g_bsum[64];
__device__ int   g_boff[64];

// ---------------- zero counters + alpha accumulators -------------------------
__global__ void zero_kernel() {
    int i = blockIdx.x * blockDim.x + threadIdx.x;
    int stride = gridDim.x * blockDim.x;
    for (int j = i; j < N_NODES * N_HEADS; j += stride) {
        g_alpha_s[j] = 0.f;
        g_alpha_d[j] = 0.f;
    }
    for (int j = i; j < N_NODES; j += stride) {
        g_deg[j] = 0;
        g_cursor[j] = 0;
    }
}

// ---------------- input conversion: x -> fp16, W -> B^T[j][k] fp16 -----------
__global__ __launch_bounds__(256) void conv_x_kernel(const float* __restrict__ x) {
    int i = blockIdx.x * blockDim.x + threadIdx.x;
    int stride = gridDim.x * blockDim.x;
    const int n4 = N_NODES * IN_DIM / 4;
    for (int j = i; j < n4; j += stride) {
        float4 v = *(const float4*)(x + j * 4);
        __half2* o = (__half2*)(g_xh + j * 4);
        o[0] = __floats2half2_rn(v.x, v.y);
        o[1] = __floats2half2_rn(v.z, v.w);
    }
}

__global__ __launch_bounds__(256) void conv_w_kernel(const float* __restrict__ W) {
    int i = blockIdx.x * blockDim.x + threadIdx.x;     // over 512*512
    int j = i >> 9, k = i & 511;                       // j = global out col
    int h = j >> 6, o = j & 63;
    g_wh[j * IN_DIM + k] = __float2half_rn(W[((long)h * IN_DIM + k) * OUT_DIM + o]);
}

// ---------------- fp16 tensor-core GEMM: feat = x @ W (+ fused alpha) --------
// A = g_xh [node][k], B^T = g_wh [j][k]; mma.m16n8k16 via ldmatrix.
// BM=128, BN=128, BK=32; 8 warps x (64x32); 3-stage cp.async pipeline.
#define GEMM_BM 128
#define GEMM_BN 128
#define GEMM_BK 32
#define GEMM_STAGES 3
#define TILE_ROW_H 40                          // halves per smem row (80 B)
#define TILE_BYTES (128 * TILE_ROW_H * 2)      // 10240 per tile
#define GEMM_SMEM_BYTES (GEMM_STAGES * 2 * TILE_BYTES)   // 61440

__device__ __forceinline__ void ldsm_x4(unsigned* r, unsigned addr) {
    asm volatile("ldmatrix.sync.aligned.m8n8.x4.shared.b16 {%0,%1,%2,%3}, [%4];"
                 : "=r"(r[0]), "=r"(r[1]), "=r"(r[2]), "=r"(r[3]) : "r"(addr));
}

__device__ __forceinline__ void mma_fp16(float* c, const unsigned* a,
                                         unsigned b0, unsigned b1) {
    asm volatile(
        "mma.sync.aligned.m16n8k16.row.col.f32.f16.f16.f32 "
        "{%0,%1,%2,%3},{%4,%5,%6,%7},{%8,%9},{%0,%1,%2,%3};"
        : "+f"(c[0]), "+f"(c[1]), "+f"(c[2]), "+f"(c[3])
        : "r"(a[0]), "r"(a[1]), "r"(a[2]), "r"(a[3]), "r"(b0), "r"(b1));
}

__device__ __forceinline__ void cp_async16(unsigned saddr, const void* g, int srcbytes) {
    asm volatile("cp.async.cg.shared.global [%0], [%1], 16, %2;\n"
                 :: "r"(saddr), "l"(g), "r"(srcbytes));
}
__device__ __forceinline__ void cp_commit() {
    asm volatile("cp.async.commit_group;\n");
}
__device__ __forceinline__ void cp_wait1() {
    asm volatile("cp.async.wait_group 1;\n");
}

__global__ __launch_bounds__(256) void gemm_fp16_kernel(const float* __restrict__ att_w) {
    extern __shared__ __half hsm[];
    unsigned sA = (unsigned)__cvta_generic_to_shared(hsm);
    unsigned sB = sA + GEMM_STAGES * TILE_BYTES;

    const int t    = threadIdx.x;
    const int lane = t & 31;
    const int wid  = t >> 5;
    const int row0 = blockIdx.y * GEMM_BM;
    const int col0 = blockIdx.x * GEMM_BN;

    const int wm = (wid & 1) * 64;
    const int wn = (wid >> 1) * 32;
    const int fr = lane >> 2;   // 0..7
    const int fc = lane & 3;    // 0..3

    // ---- cp.async mapping: 2 x 16B chunks per thread for each of A, B ----
    int crow[2], ckc[2], avalid[2];
    const __half* aptr[2];
    const __half* bptr[2];
#pragma unroll
    for (int i = 0; i < 2; i++) {
        int chunk = t + 256 * i;       // 0..511
        crow[i] = chunk >> 2;          // 0..127
        ckc[i]  = chunk & 3;           // 16B chunk within 64B row
        int gr  = row0 + crow[i];
        avalid[i] = (gr < N_NODES) ? 16 : 0;
        aptr[i] = g_xh + (long)gr * IN_DIM + ckc[i] * 8;
        bptr[i] = g_wh + (long)(col0 + crow[i]) * IN_DIM + ckc[i] * 8;
    }

    float acc[4][4][4];
#pragma unroll
    for (int mt = 0; mt < 4; mt++)
#pragma unroll
        for (int nt = 0; nt < 4; nt++)
#pragma unroll
            for (int i = 0; i < 4; i++) acc[mt][nt][i] = 0.f;

    const int NKT = IN_DIM / GEMM_BK;   // 16

    auto issue_tile = [&](int s, int buf) {
        int koff = s * GEMM_BK;
#pragma unroll
        for (int i = 0; i < 2; i++) {
            unsigned off = buf * TILE_BYTES + crow[i] * (TILE_ROW_H * 2) + ckc[i] * 16;
            cp_async16(sA + off, aptr[i] + koff, avalid[i]);
            cp_async16(sB + off, bptr[i] + koff, 16);
        }
        cp_commit();
    };

    // per-lane ldmatrix base addresses (row-major tiles, k-contiguous)
    // matrices ordered (r0-7,k0-7),(r8-15,k0-7),(r0-7,k8-15),(r8-15,k8-15)
    unsigned aaddr0 = sA + (wm + (lane & 15)) * (TILE_ROW_H * 2) + (lane >> 4) * 16;
    unsigned baddr0 = sB + (wn + (lane & 15)) * (TILE_ROW_H * 2) + (lane >> 4) * 16;

    issue_tile(0, 0);
    issue_tile(1, 1);

    for (int kt = 0; kt < NKT; kt++) {
        cp_wait1();               // tile kt resident
        __syncthreads();          // all threads done with recycled buffer

        if (kt + 2 < NKT) issue_tile(kt + 2, (kt + 2) % GEMM_STAGES);
        else              cp_commit();   // dummy group keeps wait_group 1 uniform

        unsigned stoff = (kt % GEMM_STAGES) * TILE_BYTES;
#pragma unroll
        for (int ks = 0; ks < 2; ks++) {          // two k16 steps per BK=32
            unsigned a[4][4], b[2][4];
#pragma unroll
            for (int mt = 0; mt < 4; mt++)
                ldsm_x4(a[mt], aaddr0 + stoff + mt * (16 * TILE_ROW_H * 2) + ks * 32);
#pragma unroll
            for (int np = 0; np < 2; np++)
                ldsm_x4(b[np], baddr0 + stoff + np * (16 * TILE_ROW_H * 2) + ks * 32);
            // b[np] covers nt=2np ({r0,r2}) and nt=2np+1 ({r1,r3})
#pragma unroll
            for (int mt = 0; mt < 4; mt++) {
                mma_fp16(acc[mt][0], a[mt], b[0][0], b[0][2]);
                mma_fp16(acc[mt][1], a[mt], b[0][1], b[0][3]);
                mma_fp16(acc[mt][2], a[mt], b[1][0], b[1][2]);
                mma_fp16(acc[mt][3], a[mt], b[1][1], b[1][3]);
            }
        }
    }

    // ---- epilogue: store feat as fp16 (same fragment map as m16n8k8) ----
#pragma unroll
    for (int mt = 0; mt < 4; mt++) {
#pragma unroll
        for (int nt = 0; nt < 4; nt++) {
            int row = row0 + wm + mt * 16 + fr;
            int col = col0 + wn + nt * 8 + 2 * fc;
            if (row < N_NODES)
                *(__half2*)&g_feath[(long)row * FEAT_DIM + col] =
                    __floats2half2_rn(acc[mt][nt][0], acc[mt][nt][1]);
            if (row + 8 < N_NODES)
                *(__half2*)&g_feath[(long)(row + 8) * FEAT_DIM + col] =
                    __floats2half2_rn(acc[mt][nt][2], acc[mt][nt][3]);
        }
    }

    // ---- epilogue: fused alpha partial dots (f32 accs; warp cols in one head) --
    {
        int head = (col0 + wn) >> 6;
        const float* a1 = att_w + head * (2 * OUT_DIM);
        const float* a2 = a1 + OUT_DIM;
        float s1[8], s2[8];
#pragma unroll
        for (int i = 0; i < 8; i++) { s1[i] = 0.f; s2[i] = 0.f; }
#pragma unroll
        for (int nt = 0; nt < 4; nt++) {
            int o = (wn & 63) + nt * 8 + 2 * fc;
            float w10 = a1[o], w11 = a1[o + 1];
            float w20 = a2[o], w21 = a2[o + 1];
#pragma unroll
            for (int mt = 0; mt < 4; mt++) {
                s1[mt*2]   = fmaf(acc[mt][nt][0], w10, fmaf(acc[mt][nt][1], w11, s1[mt*2]));
                s1[mt*2+1] = fmaf(acc[mt][nt][2], w10, fmaf(acc[mt][nt][3], w11, s1[mt*2+1]));
                s2[mt*2]   = fmaf(acc[mt][nt][0], w20, fmaf(acc[mt][nt][1], w21, s2[mt*2]));
                s2[mt*2+1] = fmaf(acc[mt][nt][2], w20, fmaf(acc[mt][nt][3], w21, s2[mt*2+1]));
            }
        }
#pragma unroll
        for (int i = 0; i < 8; i++) {
            s1[i] += __shfl_xor_sync(0xffffffffu, s1[i], 1);
            s1[i] += __shfl_xor_sync(0xffffffffu, s1[i], 2);
            s2[i] += __shfl_xor_sync(0xffffffffu, s2[i], 1);
            s2[i] += __shfl_xor_sync(0xffffffffu, s2[i], 2);
        }
        if (fc == 0) {
#pragma unroll
            for (int i = 0; i < 8; i++) {
                int row = row0 + wm + (i >> 1) * 16 + fr + (i & 1) * 8;
                if (row < N_NODES) {
                    atomicAdd(&g_alpha_s[row * N_HEADS + head], s1[i]);
                    atomicAdd(&g_alpha_d[row * N_HEADS + head], s2[i]);
                }
            }
        }
    }
}

// ---------------- CSR construction -------------------------------------------
__global__ void count_kernel(const int* __restrict__ src) {
    int e = blockIdx.x * blockDim.x + threadIdx.x;
    if (e < N_EDGES) atomicAdd(&g_deg[src[e]], 1);
}

// 3-phase scan: block-local scan -> scan of block sums -> add offsets
__global__ __launch_bounds__(1024) void scan1_kernel() {
    __shared__ int wsum[32];
    int tid = threadIdx.x, b = blockIdx.x;
    int i = b * 1024 + tid;
    int lane = tid & 31, wp = tid >> 5;
    int v = (i < N_NODES) ? g_deg[i] : 0;
    int x = v;
#pragma unroll
    for (int off = 1; off < 32; off <<= 1) {
        int y = __shfl_up_sync(0xffffffffu, x, off);
        if (lane >= off) x += y;
    }
    if (lane == 31) wsum[wp] = x;
    __syncthreads();
    if (wp == 0) {
        int s = wsum[lane];
#pragma unroll
        for (int off = 1; off < 32; off <<= 1) {
            int y = __shfl_up_sync(0xffffffffu, s, off);
            if (lane >= off) s += y;
        }
        wsum[lane] = s;
    }
    __syncthreads();
    int incl = x + (wp ? wsum[wp - 1] : 0);
    if (i < N_NODES) g_rowstart[i] = incl - v;   // block-local exclusive
    if (tid == 1023) g_bsum[b] = incl;
}

__global__ void scan2_kernel() {   // 1 block, 64 threads, SCAN_NB=49 sums
    __shared__ int t0;
    int tid = threadIdx.x, lane = tid & 31, wp = tid >> 5;
    int v = (tid < SCAN_NB) ? g_bsum[tid] : 0;
    int x = v;
#pragma unroll
    for (int off = 1; off < 32; off <<= 1) {
        int y = __shfl_up_sync(0xffffffffu, x, off);
        if (lane >= off) x += y;
    }
    if (wp == 0 && lane == 31) t0 = x;
    __syncthreads();
    int incl = x + (wp ? t0 : 0);
    if (tid < SCAN_NB) g_boff[tid] = incl - v;
    if (tid == SCAN_NB - 1) g_rowstart[N_NODES] = incl;
}

__global__ __launch_bounds__(1024) void scan3_kernel() {
    int i = blockIdx.x * 1024 + threadIdx.x;
    if (i < N_NODES) g_rowstart[i] += g_boff[blockIdx.x];
}

__global__ void fill_kernel(const int* __restrict__ src, const int* __restrict__ dst) {
    int e = blockIdx.x * blockDim.x + threadIdx.x;
    if (e < N_EDGES) {
        int s = src[e];
        int p = atomicAdd(&g_cursor[s], 1);
        g_csr_dst[g_rowstart[s] + p] = dst[e];
    }
}

// ---------------- per-node softmax + aggregation (fp16 gather) ---------------
// one block (256 threads = 8 warps) per src node
__global__ __launch_bounds__(256) void agg_kernel(float* __restrict__ out) {
    int n   = blockIdx.x;
    int tid = threadIdx.x;
    int rs  = g_rowstart[n];
    int deg = g_rowstart[n + 1] - rs;

    __shared__ float s_as[N_HEADS];
    __shared__ float s_inv[N_HEADS];
    __shared__ int   s_d[32];
    __shared__ float s_att[32 * N_HEADS];

    // ---- phase A: per-head exp-sum (warp w = head w); logits are O(±6), safe
    int w = tid >> 5, l = tid & 31;
    float as = g_alpha_s[n * N_HEADS + w];
    float s = 0.f;
    for (int e = l; e < deg; e += 32) {
        int d = g_csr_dst[rs + e];
        float v = as + g_alpha_d[d * N_HEADS + w];
        v = (v > 0.f) ? v : LRELU_ALPHA * v;
        s += __expf(v);
    }
#pragma unroll
    for (int o = 16; o; o >>= 1) s += __shfl_xor_sync(0xffffffffu, s, o);
    if (l == 0) {
        s_as[w]  = as;
        s_inv[w] = (deg > 0) ? (1.0f / s) : 0.f;
    }
    __syncthreads();

    // ---- phase B: weighted gather-accumulate (half2, 4B/thread/edge) ----
    float2 acc = make_float2(0.f, 0.f);
    const __half2* fh = (const __half2*)g_feath;
    int hh = tid >> 5;                    // head for columns [tid*2, tid*2+1]

    for (int c = 0; c < deg; c += 32) {
        int len = min(32, deg - c);
        __syncthreads();                  // protect s_d/s_att reuse
        if (tid < len) s_d[tid] = g_csr_dst[rs + c + tid];
        __syncthreads();
        {
            int i = tid >> 3, h = tid & 7;
            if (i < len) {
                int d = s_d[i];
                float v = s_as[h] + g_alpha_d[d * N_HEADS + h];
                v = (v > 0.f) ? v : LRELU_ALPHA * v;
                s_att[i * 8 + h] = __expf(v) * s_inv[h];
            }
        }
        __syncthreads();
        for (int i = 0; i < len; i++) {
            int d = s_d[i];
            float a = s_att[i * 8 + hh];
            float2 f = __half22float2(fh[(long)d * (FEAT_DIM / 2) + tid]);
            acc.x = fmaf(a, f.x, acc.x);
            acc.y = fmaf(a, f.y, acc.y);
        }
    }

    float2* o2 = (float2*)out;
    o2[(long)n * (FEAT_DIM / 2) + tid] =
        make_float2(fmaxf(acc.x, 0.f), fmaxf(acc.y, 0.f));
}

// ---------------- launch ------------------------------------------------------
extern "C" void kernel_launch(void* const* d_in, const int* in_sizes, int n_in,
                              void* d_out, int out_size) {
    const float* x     = (const float*)d_in[0];
    const float* W     = (const float*)d_in[1];
    const float* att_w = (const float*)d_in[2];
    const int*   src   = (const int*)d_in[3];
    const int*   dst   = (const int*)d_in[4];
    float* out = (float*)d_out;

    cudaFuncSetAttribute(gemm_fp16_kernel,
                         cudaFuncAttributeMaxDynamicSharedMemorySize, GEMM_SMEM_BYTES);

    // gemm placed 4th: ncu empirically captures the 4th launch
    zero_kernel<<<512, 256>>>();
    conv_x_kernel<<<2048, 256>>>(x);
    conv_w_kernel<<<(FEAT_DIM * IN_DIM) / 256, 256>>>(W);
    gemm_fp16_kernel<<<dim3(FEAT_DIM / GEMM_BN, (N_NODES + GEMM_BM - 1) / GEMM_BM),
                      256, GEMM_SMEM_BYTES>>>(att_w);
    count_kernel<<<(N_EDGES + 255) / 256, 256>>>(src);
    scan1_kernel<<<SCAN_NB, 1024>>>();
    scan2_kernel<<<1, 64>>>();
    scan3_kernel<<<SCAN_NB, 1024>>>();
    fill_kernel<<<(N_EDGES + 255) / 256, 256>>>(src, dst);
    agg_kernel<<<N_NODES, 256>>>(out);
}